// round 1
// baseline (speedup 1.0000x reference)
#include <cuda_runtime.h>
#include <cuda_bf16.h>
#include <cstdint>

// Problem constants
#define B_ 16
#define T_ 16384
#define D_ 256
#define S_ 4
#define TILE 128
#define KT 64
#define KSPLIT 8
#define KCHUNK (T_ / KSPLIT)   // 2048
#define PITCH 136              // 128 + 8 pad -> 272B rows, conflict-free ldmatrix.trans
#define MS (KT * PITCH)        // elements per smem matrix stage

// Scratch (device globals: allocation-free rule)
__device__ __nv_bfloat16 g_V[(size_t)B_ * T_ * D_];     // normalized V, bf16
__device__ unsigned char g_cls[B_ * T_];                 // speaker class per row
__device__ float g_Gvv[B_ * 3 * TILE * TILE];            // 3 symmetric tiles per batch
__device__ float g_Gvy[B_ * D_ * S_];
__device__ float g_part[64];

// ---------------------------------------------------------------------------
// K1: row-wise L2 normalize fp32 -> bf16, extract class index from one-hot
// 1 warp per row (256 cols = 32 lanes x 8)
// ---------------------------------------------------------------------------
__global__ __launch_bounds__(256) void k_norm(const float* __restrict__ emb,
                                              const float* __restrict__ lab) {
    int row  = blockIdx.x * 8 + (threadIdx.x >> 5);
    int lane = threadIdx.x & 31;
    const float4* src = reinterpret_cast<const float4*>(emb) + (size_t)row * (D_ / 4) + lane * 2;
    float4 v0 = src[0];
    float4 v1 = src[1];
    float ss = v0.x*v0.x + v0.y*v0.y + v0.z*v0.z + v0.w*v0.w
             + v1.x*v1.x + v1.y*v1.y + v1.z*v1.z + v1.w*v1.w;
    #pragma unroll
    for (int o = 16; o; o >>= 1) ss += __shfl_xor_sync(0xffffffffu, ss, o);
    float sc = 1.0f / fmaxf(sqrtf(ss), 1e-12f);

    __nv_bfloat162 p0 = __floats2bfloat162_rn(v0.x * sc, v0.y * sc);
    __nv_bfloat162 p1 = __floats2bfloat162_rn(v0.z * sc, v0.w * sc);
    __nv_bfloat162 p2 = __floats2bfloat162_rn(v1.x * sc, v1.y * sc);
    __nv_bfloat162 p3 = __floats2bfloat162_rn(v1.z * sc, v1.w * sc);
    uint4 pk;
    pk.x = *reinterpret_cast<uint32_t*>(&p0);
    pk.y = *reinterpret_cast<uint32_t*>(&p1);
    pk.z = *reinterpret_cast<uint32_t*>(&p2);
    pk.w = *reinterpret_cast<uint32_t*>(&p3);
    reinterpret_cast<uint4*>(g_V)[(size_t)row * (D_ / 8) + lane] = pk;

    if (lane == 0) {
        float4 lb = reinterpret_cast<const float4*>(lab)[row];
        g_cls[row] = lb.y > 0.5f ? 1 : (lb.z > 0.5f ? 2 : (lb.w > 0.5f ? 3 : 0));
    }
}

// ---------------------------------------------------------------------------
// K0: zero the atomic-accumulated scratch
// ---------------------------------------------------------------------------
__global__ void k_zero() {
    int i = blockIdx.x * 256 + threadIdx.x;
    if (i < B_ * 3 * TILE * TILE) g_Gvv[i] = 0.0f;
    if (i < B_ * D_ * S_) g_Gvy[i] = 0.0f;
}

// ---------------------------------------------------------------------------
// PTX helpers
// ---------------------------------------------------------------------------
__device__ __forceinline__ void cp16(__nv_bfloat16* dst, const __nv_bfloat16* src) {
    unsigned d = (unsigned)__cvta_generic_to_shared(dst);
    asm volatile("cp.async.cg.shared.global [%0], [%1], 16;\n" :: "r"(d), "l"(src));
}
__device__ __forceinline__ void cp_commit() { asm volatile("cp.async.commit_group;\n"); }
template <int N> __device__ __forceinline__ void cp_wait() {
    asm volatile("cp.async.wait_group %0;\n" :: "n"(N));
}
__device__ __forceinline__ void ldsm4t(uint32_t* r, const __nv_bfloat16* p) {
    unsigned a = (unsigned)__cvta_generic_to_shared(p);
    asm volatile("ldmatrix.sync.aligned.m8n8.x4.trans.shared.b16 {%0,%1,%2,%3}, [%4];\n"
                 : "=r"(r[0]), "=r"(r[1]), "=r"(r[2]), "=r"(r[3]) : "r"(a));
}
__device__ __forceinline__ void mma_bf16(float* c, const uint32_t* a, const uint32_t* b) {
    asm volatile("mma.sync.aligned.m16n8k16.row.col.f32.bf16.bf16.f32 "
                 "{%0,%1,%2,%3},{%4,%5,%6,%7},{%8,%9},{%0,%1,%2,%3};\n"
                 : "+f"(c[0]), "+f"(c[1]), "+f"(c[2]), "+f"(c[3])
                 : "r"(a[0]), "r"(a[1]), "r"(a[2]), "r"(a[3]), "r"(b[0]), "r"(b[1]));
}

// ---------------------------------------------------------------------------
// K2: Gram tiles Gvv = V^T V. grid.x = 48 (batch*3 + tile), grid.y = KSPLIT.
// tile 0 -> (ti,tj)=(0,0), 1 -> (1,0), 2 -> (1,1). CTA tile 128x128, K-chunk 2048.
// 8 warps: warp grid 4(m) x 2(n), warp tile 32x64. fp32 atomicAdd partials.
// ---------------------------------------------------------------------------
__global__ __launch_bounds__(256) void k_gram() {
    extern __shared__ __nv_bfloat16 sm[];
    int bt   = blockIdx.x;
    int b    = bt / 3, tile = bt % 3;
    int ti   = (tile == 0) ? 0 : 1;
    int tj   = (tile == 2) ? 1 : 0;
    bool diag = (ti == tj);
    int kc   = blockIdx.y;
    int tid  = threadIdx.x;
    const __nv_bfloat16* gv = g_V + (size_t)(b * T_ + kc * KCHUNK) * D_;

    int wid = tid >> 5, lane = tid & 31;
    int wm = (wid & 3) * 32;
    int wn = (wid >> 2) * 64;
    int q = lane >> 3, rr = lane & 7;

    float acc[2][8][4];
    #pragma unroll
    for (int mi = 0; mi < 2; mi++)
        #pragma unroll
        for (int ni = 0; ni < 8; ni++)
            #pragma unroll
            for (int x = 0; x < 4; x++) acc[mi][ni][x] = 0.0f;

    auto load_stage = [&](int st, int kofs) {
        const __nv_bfloat16* ga = gv + (size_t)kofs * D_ + ti * TILE;
        __nv_bfloat16* sa = sm + st * MS;
        #pragma unroll
        for (int i = 0; i < 4; i++) {
            int c = tid + i * 256;
            int r = c >> 4, cc = c & 15;
            cp16(sa + r * PITCH + cc * 8, ga + r * D_ + cc * 8);
        }
        if (!diag) {
            const __nv_bfloat16* gb = gv + (size_t)kofs * D_ + tj * TILE;
            __nv_bfloat16* sb = sm + (2 + st) * MS;
            #pragma unroll
            for (int i = 0; i < 4; i++) {
                int c = tid + i * 256;
                int r = c >> 4, cc = c & 15;
                cp16(sb + r * PITCH + cc * 8, gb + r * D_ + cc * 8);
            }
        }
        cp_commit();
    };

    load_stage(0, 0);
    const int NIT = KCHUNK / KT;  // 32
    for (int it = 0; it < NIT; ++it) {
        if (it + 1 < NIT) { load_stage((it + 1) & 1, (it + 1) * KT); cp_wait<1>(); }
        else              { cp_wait<0>(); }
        __syncthreads();
        const __nv_bfloat16* As = sm + (it & 1) * MS;
        const __nv_bfloat16* Bs = diag ? As : sm + (2 + (it & 1)) * MS;
        #pragma unroll
        for (int ks = 0; ks < KT / 16; ++ks) {
            // A fragments: need A[m][k] = V[k][dm+m] -> ldmatrix.trans of [k][d] tile
            uint32_t af[2][4];
            #pragma unroll
            for (int mi = 0; mi < 2; mi++) {
                int dm   = wm + mi * 16;
                int krow = ks * 16 + ((q & 2) ? 8 : 0) + rr;
                int col  = dm + ((q & 1) ? 8 : 0);
                ldsm4t(af[mi], As + krow * PITCH + col);
            }
            // B fragments: B[k][n] = V[k][dn+n] -> same trans pattern, paired per x4
            uint32_t bfr[8][2];
            #pragma unroll
            for (int j = 0; j < 4; j++) {
                int n0   = wn + j * 16;
                int krow = ks * 16 + ((q & 1) ? 8 : 0) + rr;
                int col  = n0 + ((q & 2) ? 8 : 0);
                uint32_t t4[4];
                ldsm4t(t4, Bs + krow * PITCH + col);
                bfr[2 * j][0]     = t4[0]; bfr[2 * j][1]     = t4[1];
                bfr[2 * j + 1][0] = t4[2]; bfr[2 * j + 1][1] = t4[3];
            }
            #pragma unroll
            for (int mi = 0; mi < 2; mi++)
                #pragma unroll
                for (int ni = 0; ni < 8; ni++)
                    mma_bf16(acc[mi][ni], af[mi], bfr[ni]);
        }
        __syncthreads();
    }

    // Epilogue: accumulate partial tile into global scratch
    int gid = lane >> 2, tig = lane & 3;
    float* gdst = g_Gvv + (size_t)bt * TILE * TILE;
    #pragma unroll
    for (int mi = 0; mi < 2; mi++) {
        #pragma unroll
        for (int ni = 0; ni < 8; ni++) {
            int m = wm + mi * 16 + gid;
            int n = wn + ni * 8 + tig * 2;
            float* p = gdst + m * TILE + n;
            atomicAdd(p + 0, acc[mi][ni][0]);
            atomicAdd(p + 1, acc[mi][ni][1]);
            atomicAdd(p + 8 * TILE + 0, acc[mi][ni][2]);
            atomicAdd(p + 8 * TILE + 1, acc[mi][ni][3]);
        }
    }
}

// ---------------------------------------------------------------------------
// K3: Gvy[b][d][s] = sum over t in class s of V[t][d] (Y one-hot)
// grid = 16 batches x 4 d-chunks(64) x 8 t-chunks(2048), 256 threads
// ---------------------------------------------------------------------------
__global__ __launch_bounds__(256) void k_gvy() {
    int bid = blockIdx.x;
    int b = bid >> 5;
    int rem = bid & 31;
    int dch = rem >> 3, tch = rem & 7;
    int dcol = dch * 64 + (threadIdx.x & 63);
    int tsub = threadIdx.x >> 6;
    float a0 = 0, a1 = 0, a2 = 0, a3 = 0;
    const __nv_bfloat16* base = g_V + (size_t)b * T_ * D_ + dcol;
    const unsigned char* cb = g_cls + b * T_;
    int t0 = tch * 2048;
    for (int t = t0 + tsub; t < t0 + 2048; t += 4) {
        float v = __bfloat162float(base[(size_t)t * D_]);
        int s = cb[t];
        a0 += (s == 0) ? v : 0.0f;
        a1 += (s == 1) ? v : 0.0f;
        a2 += (s == 2) ? v : 0.0f;
        a3 += (s == 3) ? v : 0.0f;
    }
    float* dst = g_Gvy + (b * D_ + dcol) * S_;
    atomicAdd(dst + 0, a0);
    atomicAdd(dst + 1, a1);
    atomicAdd(dst + 2, a2);
    atomicAdd(dst + 3, a3);
}

// ---------------------------------------------------------------------------
// Reductions
// ---------------------------------------------------------------------------
__device__ float blockSum(float v) {
    __shared__ float sw[8];
    int lane = threadIdx.x & 31, w = threadIdx.x >> 5;
    __syncthreads();
    #pragma unroll
    for (int o = 16; o; o >>= 1) v += __shfl_xor_sync(0xffffffffu, v, o);
    if (lane == 0) sw[w] = v;
    __syncthreads();
    v = (threadIdx.x < 8) ? sw[threadIdx.x] : 0.0f;
    if (w == 0)
        #pragma unroll
        for (int o = 4; o; o >>= 1) v += __shfl_xor_sync(0xffu, v, o);
    return v;  // valid in thread 0
}

__global__ __launch_bounds__(256) void k_red1() {
    int bid = blockIdx.x, tid = threadIdx.x;
    if (bid < 48) {
        const float* g = g_Gvv + (size_t)bid * TILE * TILE;
        float total = 0.0f;
        for (int i = tid; i < TILE * TILE; i += 256) { float x = g[i]; total += x * x; }
        total = blockSum(total);
        if (tid == 0) {
            float w = (bid % 3 == 1) ? 2.0f : 1.0f;  // off-diagonal tile counts twice
            g_part[bid] = w * total;
        }
    } else {
        int b = bid - 48;
        float gy = 0.0f;
        for (int i = tid; i < D_ * S_; i += 256) { float x = g_Gvy[b * D_ * S_ + i]; gy += x * x; }
        float c0 = 0, c1 = 0, c2 = 0, c3 = 0;
        for (int t = tid; t < T_; t += 256) {
            int s = g_cls[b * T_ + t];
            c0 += (s == 0); c1 += (s == 1); c2 += (s == 2); c3 += (s == 3);
        }
        gy = blockSum(gy);
        c0 = blockSum(c0); c1 = blockSum(c1); c2 = blockSum(c2); c3 = blockSum(c3);
        if (tid == 0)
            g_part[bid] = -2.0f * gy + c0 * c0 + c1 * c1 + c2 * c2 + c3 * c3;
    }
}

__global__ void k_final(float* out) {
    int tid = threadIdx.x;  // 64 threads
    float v = g_part[tid];
    #pragma unroll
    for (int o = 16; o; o >>= 1) v += __shfl_xor_sync(0xffffffffu, v, o);
    __shared__ float s2[2];
    if ((tid & 31) == 0) s2[tid >> 5] = v;
    __syncthreads();
    if (tid == 0) {
        float total = s2[0] + s2[1];
        // divide by T*T*B = 2^28 * 2^4 = 2^32 (exact power of two)
        out[0] = total * 2.3283064365386963e-10f;
    }
}

// ---------------------------------------------------------------------------
extern "C" void kernel_launch(void* const* d_in, const int* in_sizes, int n_in,
                              void* d_out, int out_size) {
    const float* emb = (const float*)d_in[0];
    const float* lab = (const float*)d_in[1];
    float* out = (float*)d_out;
    (void)in_sizes; (void)n_in; (void)out_size;

    const int smem_bytes = 4 * MS * (int)sizeof(__nv_bfloat16);  // 69632
    cudaFuncSetAttribute(k_gram, cudaFuncAttributeMaxDynamicSharedMemorySize, smem_bytes);

    k_zero<<<(B_ * 3 * TILE * TILE + 255) / 256, 256>>>();
    k_norm<<<(B_ * T_) / 8, 256>>>(emb, lab);
    dim3 g2(48, KSPLIT);
    k_gram<<<g2, 256, smem_bytes>>>();
    k_gvy<<<512, 256>>>();
    k_red1<<<64, 256>>>();
    k_final<<<1, 64>>>(out);
}